// round 2
// baseline (speedup 1.0000x reference)
#include <cuda_runtime.h>
#include <math.h>

#define NTOK 4096
#define EDIM 1024
#define HDIM 2730
#define HS   2752        // padded h row stride (16B-aligned float4 rows)
#define NEXP 8
#define CAP  4096

// ---------------- scratch (device globals; no allocations) ----------------
__device__ int   g_cnt[NEXP];
__device__ int   g_slot[NEXP][CAP];      // (token<<1) | rank
__device__ float g_wt[NEXP][CAP];        // combine weight for that slot
__device__ float g_h[(size_t)NEXP * CAP * HS];        // SwiGLU activations (~361 MB)
__device__ float g_contrib[2][(size_t)NTOK * EDIM];   // per-rank expert outputs

// ---------------- kernel 0: reset counters ----------------
__global__ void k_zero() {
    if (threadIdx.x < NEXP) g_cnt[threadIdx.x] = 0;
}

// ---------------- kernel 1: router (one warp per token) ----------------
__global__ void k_router(const float* __restrict__ x, const float* __restrict__ Wr) {
    int token = blockIdx.x * blockDim.y + threadIdx.y;
    int lane  = threadIdx.x;
    const float* xr = x + (size_t)token * EDIM;

    float acc[NEXP];
    #pragma unroll
    for (int e = 0; e < NEXP; e++) acc[e] = 0.f;

    for (int i = lane; i < EDIM; i += 32) {
        float xv = xr[i];
        #pragma unroll
        for (int e = 0; e < NEXP; e++) acc[e] = fmaf(xv, Wr[e * EDIM + i], acc[e]);
    }
    #pragma unroll
    for (int off = 16; off > 0; off >>= 1) {
        #pragma unroll
        for (int e = 0; e < NEXP; e++)
            acc[e] += __shfl_down_sync(0xffffffffu, acc[e], off);
    }
    if (lane == 0) {
        // top-2, lowest index wins ties (matches jax.lax.top_k)
        int i0 = 0; float v0 = acc[0];
        #pragma unroll
        for (int e = 1; e < NEXP; e++) if (acc[e] > v0) { v0 = acc[e]; i0 = e; }
        int i1 = -1; float v1 = -3.0e38f;
        #pragma unroll
        for (int e = 0; e < NEXP; e++) if (e != i0 && acc[e] > v1) { v1 = acc[e]; i1 = e; }
        float t  = expf(v1 - v0);             // <= 1
        float w0 = 1.f / (1.f + t);
        float w1 = t   / (1.f + t);
        int s0 = atomicAdd(&g_cnt[i0], 1);
        g_slot[i0][s0] = (token << 1);     g_wt[i0][s0] = w0;
        int s1 = atomicAdd(&g_cnt[i1], 1);
        g_slot[i1][s1] = (token << 1) | 1; g_wt[i1][s1] = w1;
    }
}

// ---------------- kernel 2: fused GEMM1  h = silu(X Wv + bv) * (X Wg + bg) ----------
// tiles: BM=128, BN=64 (over H), BK=16; 256 threads; 8x4 microtile per matrix
__global__ __launch_bounds__(256, 2)
void k_gemm1(const float* __restrict__ x,
             const float* __restrict__ Wv, const float* __restrict__ bv,
             const float* __restrict__ Wg, const float* __restrict__ bg) {
    const int e  = blockIdx.z;
    const int mt = blockIdx.y;
    const int nt = blockIdx.x;
    const int cnt = g_cnt[e];
    if (mt * 128 >= cnt) return;

    __shared__ float As [16][128];
    __shared__ float Bvs[16][64];
    __shared__ float Bgs[16][64];

    const int t  = threadIdx.x;
    // A load: 2 threads per row, 2 x float4 each (transposed into smem)
    const int ar = t >> 1;
    const int ac = (t & 1) * 8;
    const int aslot = mt * 128 + ar;
    const float* aptr = nullptr;
    if (aslot < cnt) {
        int tok = g_slot[e][aslot] >> 1;
        aptr = x + (size_t)tok * EDIM;
    }
    // B load: 16 k-rows x 16 lanes, each lane 4 strided columns (coalesced)
    const int bk = t >> 4;        // 0..15
    const int bc = t & 15;        // 0..15 ; columns bc, bc+16, bc+32, bc+48
    const int n0 = nt * 64;
    const float* wvp = Wv + (size_t)e * EDIM * HDIM;
    const float* wgp = Wg + (size_t)e * EDIM * HDIM;

    const int tx = t & 15, ty = t >> 4;

    float accv[8][4], accg[8][4];
    #pragma unroll
    for (int i = 0; i < 8; i++)
        #pragma unroll
        for (int j = 0; j < 4; j++) { accv[i][j] = 0.f; accg[i][j] = 0.f; }

    float4 pa0, pa1;
    float pv[4], pg[4];

    // prime pipeline
    {
        if (aptr) {
            pa0 = *(const float4*)(aptr + 0 + ac);
            pa1 = *(const float4*)(aptr + 0 + ac + 4);
        } else { pa0 = make_float4(0,0,0,0); pa1 = pa0; }
        #pragma unroll
        for (int j = 0; j < 4; j++) {
            int n = n0 + bc + j * 16;
            size_t off = (size_t)bk * HDIM + n;
            bool ok = (n < HDIM);
            pv[j] = ok ? wvp[off] : 0.f;
            pg[j] = ok ? wgp[off] : 0.f;
        }
    }

    for (int k0 = 0; k0 < EDIM; k0 += 16) {
        // stage registers -> smem
        As[ac+0][ar] = pa0.x; As[ac+1][ar] = pa0.y; As[ac+2][ar] = pa0.z; As[ac+3][ar] = pa0.w;
        As[ac+4][ar] = pa1.x; As[ac+5][ar] = pa1.y; As[ac+6][ar] = pa1.z; As[ac+7][ar] = pa1.w;
        #pragma unroll
        for (int j = 0; j < 4; j++) { Bvs[bk][bc + j*16] = pv[j]; Bgs[bk][bc + j*16] = pg[j]; }
        __syncthreads();

        // prefetch next tile
        if (k0 + 16 < EDIM) {
            int kn = k0 + 16;
            if (aptr) {
                pa0 = *(const float4*)(aptr + kn + ac);
                pa1 = *(const float4*)(aptr + kn + ac + 4);
            } else { pa0 = make_float4(0,0,0,0); pa1 = pa0; }
            #pragma unroll
            for (int j = 0; j < 4; j++) {
                int n = n0 + bc + j * 16;
                size_t off = (size_t)(kn + bk) * HDIM + n;
                bool ok = (n < HDIM);
                pv[j] = ok ? wvp[off] : 0.f;
                pg[j] = ok ? wgp[off] : 0.f;
            }
        }

        #pragma unroll
        for (int kk = 0; kk < 16; kk++) {
            float a[8], bv4[4], bg4[4];
            #pragma unroll
            for (int i = 0; i < 8; i++) a[i] = As[kk][ty*8 + i];
            #pragma unroll
            for (int j = 0; j < 4; j++) { bv4[j] = Bvs[kk][tx*4 + j]; bg4[j] = Bgs[kk][tx*4 + j]; }
            #pragma unroll
            for (int i = 0; i < 8; i++)
                #pragma unroll
                for (int j = 0; j < 4; j++) {
                    accv[i][j] = fmaf(a[i], bv4[j], accv[i][j]);
                    accg[i][j] = fmaf(a[i], bg4[j], accg[i][j]);
                }
        }
        __syncthreads();
    }

    // epilogue: SwiGLU, write h (zero in pad columns [HDIM, HS) of last tile)
    #pragma unroll
    for (int i = 0; i < 8; i++) {
        int s = mt * 128 + ty * 8 + i;
        if (s >= cnt) continue;
        float* hrow = g_h + ((size_t)e * CAP + s) * HS;
        #pragma unroll
        for (int j = 0; j < 4; j++) {
            int n = n0 + tx * 4 + j;
            float val = 0.f;
            if (n < HDIM) {
                float hv = accv[i][j] + bv[(size_t)e * HDIM + n];
                float hg = accg[i][j] + bg[(size_t)e * HDIM + n];
                float sig = 1.f / (1.f + expf(-hv));
                val = hv * sig * hg;
            }
            if (n < HS) hrow[n] = val;
        }
    }
}

// ---------------- kernel 3: GEMM2  contrib[rank][tok] = w * (h Wo + bo) -----------
// tiles: BM=128, BN=128 (over E), BK=16; 256 threads; 8x8 microtile
#define KT2 2736   // 171 * 16 ; h pad columns are zero, Wo rows >= HDIM zero-filled
__global__ __launch_bounds__(256, 2)
void k_gemm2(const float* __restrict__ Wo, const float* __restrict__ bo) {
    const int e  = blockIdx.z;
    const int mt = blockIdx.y;
    const int nt = blockIdx.x;
    const int cnt = g_cnt[e];
    if (mt * 128 >= cnt) return;

    __shared__ float As[16][128];
    __shared__ float Bs[16][128];

    const int t  = threadIdx.x;
    const int ar = t >> 1;
    const int ac = (t & 1) * 8;
    const int aslot = mt * 128 + ar;
    const float* aptr = (aslot < cnt) ? (g_h + ((size_t)e * CAP + aslot) * HS) : nullptr;

    const int bk = t >> 4;         // 0..15
    const int bc = (t & 15) * 8;   // 0..120
    const int n0 = nt * 128;
    const float* wop = Wo + (size_t)e * HDIM * EDIM;

    const int tx = t & 15, ty = t >> 4;

    float acc[8][8];
    #pragma unroll
    for (int i = 0; i < 8; i++)
        #pragma unroll
        for (int j = 0; j < 8; j++) acc[i][j] = 0.f;

    float4 pa0, pa1, pb0, pb1;
    {
        if (aptr) {
            pa0 = *(const float4*)(aptr + ac);
            pa1 = *(const float4*)(aptr + ac + 4);
        } else { pa0 = make_float4(0,0,0,0); pa1 = pa0; }
        if (bk < HDIM) {
            const float* bp = wop + (size_t)bk * EDIM + n0 + bc;
            pb0 = *(const float4*)(bp);
            pb1 = *(const float4*)(bp + 4);
        } else { pb0 = make_float4(0,0,0,0); pb1 = pb0; }
    }

    for (int k0 = 0; k0 < KT2; k0 += 16) {
        As[ac+0][ar] = pa0.x; As[ac+1][ar] = pa0.y; As[ac+2][ar] = pa0.z; As[ac+3][ar] = pa0.w;
        As[ac+4][ar] = pa1.x; As[ac+5][ar] = pa1.y; As[ac+6][ar] = pa1.z; As[ac+7][ar] = pa1.w;
        *(float4*)&Bs[bk][bc]     = pb0;
        *(float4*)&Bs[bk][bc + 4] = pb1;
        __syncthreads();

        if (k0 + 16 < KT2) {
            int kn = k0 + 16;
            if (aptr) {
                pa0 = *(const float4*)(aptr + kn + ac);
                pa1 = *(const float4*)(aptr + kn + ac + 4);
            } else { pa0 = make_float4(0,0,0,0); pa1 = pa0; }
            if (kn + bk < HDIM) {
                const float* bp = wop + (size_t)(kn + bk) * EDIM + n0 + bc;
                pb0 = *(const float4*)(bp);
                pb1 = *(const float4*)(bp + 4);
            } else { pb0 = make_float4(0,0,0,0); pb1 = pb0; }
        }

        #pragma unroll
        for (int kk = 0; kk < 16; kk++) {
            float a[8], b[8];
            #pragma unroll
            for (int i = 0; i < 8; i++) a[i] = As[kk][ty*8 + i];
            #pragma unroll
            for (int j = 0; j < 8; j++) b[j] = Bs[kk][tx*8 + j];
            #pragma unroll
            for (int i = 0; i < 8; i++)
                #pragma unroll
                for (int j = 0; j < 8; j++)
                    acc[i][j] = fmaf(a[i], b[j], acc[i][j]);
        }
        __syncthreads();
    }

    // epilogue: scale by combine weight, plain store (unique per (token,rank))
    #pragma unroll
    for (int i = 0; i < 8; i++) {
        int s = mt * 128 + ty * 8 + i;
        if (s >= cnt) continue;
        int   info = g_slot[e][s];
        int   tok  = info >> 1;
        int   rank = info & 1;
        float w    = g_wt[e][s];
        float* dst = g_contrib[rank] + (size_t)tok * EDIM;
        #pragma unroll
        for (int j = 0; j < 8; j++) {
            int n = n0 + tx * 8 + j;
            dst[n] = w * (acc[i][j] + bo[(size_t)e * EDIM + n]);
        }
    }
}

// ---------------- kernel 4: residual + LayerNorm ----------------
__global__ void k_ln(const float* __restrict__ x,
                     const float* __restrict__ lng, const float* __restrict__ lnb,
                     float* __restrict__ out) {
    const int tok = blockIdx.x;
    const int t   = threadIdx.x;     // 256
    const float* xr = x + (size_t)tok * EDIM;
    const float* c0 = g_contrib[0] + (size_t)tok * EDIM;
    const float* c1 = g_contrib[1] + (size_t)tok * EDIM;

    float v[4];
    float s = 0.f;
    #pragma unroll
    for (int i = 0; i < 4; i++) {
        int idx = t + i * 256;
        v[i] = xr[idx] + c0[idx] + c1[idx];
        s += v[i];
    }
    __shared__ float red[256];
    red[t] = s; __syncthreads();
    #pragma unroll
    for (int off = 128; off > 0; off >>= 1) {
        if (t < off) red[t] += red[t + off];
        __syncthreads();
    }
    float mu = red[0] * (1.f / 1024.f);
    __syncthreads();

    float sq = 0.f;
    #pragma unroll
    for (int i = 0; i < 4; i++) { float d = v[i] - mu; sq += d * d; }
    red[t] = sq; __syncthreads();
    #pragma unroll
    for (int off = 128; off > 0; off >>= 1) {
        if (t < off) red[t] += red[t + off];
        __syncthreads();
    }
    float var  = red[0] * (1.f / 1024.f);
    float rstd = rsqrtf(var + 1e-5f);

    #pragma unroll
    for (int i = 0; i < 4; i++) {
        int idx = t + i * 256;
        out[(size_t)tok * EDIM + idx] = lng[idx] * (v[i] - mu) * rstd + lnb[idx];
    }
}

// ---------------- launcher ----------------
extern "C" void kernel_launch(void* const* d_in, const int* in_sizes, int n_in,
                              void* d_out, int out_size) {
    const float* x   = (const float*)d_in[0];
    const float* Wr  = (const float*)d_in[1];
    const float* Wv  = (const float*)d_in[2];
    const float* bv  = (const float*)d_in[3];
    const float* Wg  = (const float*)d_in[4];
    const float* bg  = (const float*)d_in[5];
    const float* Wo  = (const float*)d_in[6];
    const float* bo  = (const float*)d_in[7];
    const float* lng = (const float*)d_in[8];
    const float* lnb = (const float*)d_in[9];
    float* out = (float*)d_out;

    k_zero  <<<1, 32>>>();
    k_router<<<NTOK / 8, dim3(32, 8)>>>(x, Wr);
    k_gemm1 <<<dim3(43, 32, NEXP), 256>>>(x, Wv, bv, Wg, bg);
    k_gemm2 <<<dim3(8, 32, NEXP), 256>>>(Wo, bo);
    k_ln    <<<NTOK, 256>>>(x, lng, lnb, out);
}

// round 5
// speedup vs baseline: 1.0005x; 1.0005x over previous
#include <cuda_runtime.h>
#include <math.h>

#define NTOK 4096
#define EDIM 1024
#define HDIM 2730
#define HS   2752        // padded h row stride (16B-aligned float4 rows)
#define NEXP 8
#define CAP  4096

// ---------------- scratch (device globals; no allocations) ----------------
__device__ int   g_cnt[NEXP];
__device__ int   g_slot[NEXP][CAP];      // (token<<1) | rank
__device__ float g_wt[NEXP][CAP];        // combine weight for that slot
__device__ float g_h[(size_t)NEXP * CAP * HS];        // SwiGLU activations (~361 MB)
__device__ float g_contrib[2][(size_t)NTOK * EDIM];   // per-rank expert outputs

// ---------------- kernel 0: reset counters ----------------
__global__ void k_zero() {
    if (threadIdx.x < NEXP) g_cnt[threadIdx.x] = 0;
}

// ---------------- kernel 1: router (one warp per token) ----------------
__global__ void k_router(const float* __restrict__ x, const float* __restrict__ Wr) {
    int token = blockIdx.x * blockDim.y + threadIdx.y;
    int lane  = threadIdx.x;
    const float* xr = x + (size_t)token * EDIM;

    float acc[NEXP];
    #pragma unroll
    for (int e = 0; e < NEXP; e++) acc[e] = 0.f;

    for (int i = lane; i < EDIM; i += 32) {
        float xv = xr[i];
        #pragma unroll
        for (int e = 0; e < NEXP; e++) acc[e] = fmaf(xv, Wr[e * EDIM + i], acc[e]);
    }
    #pragma unroll
    for (int off = 16; off > 0; off >>= 1) {
        #pragma unroll
        for (int e = 0; e < NEXP; e++)
            acc[e] += __shfl_down_sync(0xffffffffu, acc[e], off);
    }
    if (lane == 0) {
        // top-2, lowest index wins ties (matches jax.lax.top_k)
        int i0 = 0; float v0 = acc[0];
        #pragma unroll
        for (int e = 1; e < NEXP; e++) if (acc[e] > v0) { v0 = acc[e]; i0 = e; }
        int i1 = -1; float v1 = -3.0e38f;
        #pragma unroll
        for (int e = 0; e < NEXP; e++) if (e != i0 && acc[e] > v1) { v1 = acc[e]; i1 = e; }
        float t  = expf(v1 - v0);             // <= 1
        float w0 = 1.f / (1.f + t);
        float w1 = t   / (1.f + t);
        int s0 = atomicAdd(&g_cnt[i0], 1);
        g_slot[i0][s0] = (token << 1);     g_wt[i0][s0] = w0;
        int s1 = atomicAdd(&g_cnt[i1], 1);
        g_slot[i1][s1] = (token << 1) | 1; g_wt[i1][s1] = w1;
    }
}

// ---------------- kernel 2: fused GEMM1  h = silu(X Wv + bv) * (X Wg + bg) ----------
// tiles: BM=128, BN=64 (over H), BK=16; 256 threads; 8x4 microtile per matrix
__global__ __launch_bounds__(256, 2)
void k_gemm1(const float* __restrict__ x,
             const float* __restrict__ Wv, const float* __restrict__ bv,
             const float* __restrict__ Wg, const float* __restrict__ bg) {
    const int e  = blockIdx.z;
    const int mt = blockIdx.y;
    const int nt = blockIdx.x;
    const int cnt = g_cnt[e];
    if (mt * 128 >= cnt) return;

    __shared__ float As [16][128];
    __shared__ float Bvs[16][64];
    __shared__ float Bgs[16][64];

    const int t  = threadIdx.x;
    // A load: 2 threads per row, 2 x float4 each (transposed into smem)
    const int ar = t >> 1;
    const int ac = (t & 1) * 8;
    const int aslot = mt * 128 + ar;
    const float* aptr = nullptr;
    if (aslot < cnt) {
        int tok = g_slot[e][aslot] >> 1;
        aptr = x + (size_t)tok * EDIM;
    }
    // B load: 16 k-rows x 16 lanes, each lane 4 strided columns (coalesced)
    const int bk = t >> 4;        // 0..15
    const int bc = t & 15;        // 0..15 ; columns bc, bc+16, bc+32, bc+48
    const int n0 = nt * 64;
    const float* wvp = Wv + (size_t)e * EDIM * HDIM;
    const float* wgp = Wg + (size_t)e * EDIM * HDIM;

    const int tx = t & 15, ty = t >> 4;

    float accv[8][4], accg[8][4];
    #pragma unroll
    for (int i = 0; i < 8; i++)
        #pragma unroll
        for (int j = 0; j < 4; j++) { accv[i][j] = 0.f; accg[i][j] = 0.f; }

    float4 pa0, pa1;
    float pv[4], pg[4];

    // prime pipeline
    {
        if (aptr) {
            pa0 = *(const float4*)(aptr + 0 + ac);
            pa1 = *(const float4*)(aptr + 0 + ac + 4);
        } else { pa0 = make_float4(0,0,0,0); pa1 = pa0; }
        #pragma unroll
        for (int j = 0; j < 4; j++) {
            int n = n0 + bc + j * 16;
            size_t off = (size_t)bk * HDIM + n;
            bool ok = (n < HDIM);
            pv[j] = ok ? wvp[off] : 0.f;
            pg[j] = ok ? wgp[off] : 0.f;
        }
    }

    for (int k0 = 0; k0 < EDIM; k0 += 16) {
        // stage registers -> smem
        As[ac+0][ar] = pa0.x; As[ac+1][ar] = pa0.y; As[ac+2][ar] = pa0.z; As[ac+3][ar] = pa0.w;
        As[ac+4][ar] = pa1.x; As[ac+5][ar] = pa1.y; As[ac+6][ar] = pa1.z; As[ac+7][ar] = pa1.w;
        #pragma unroll
        for (int j = 0; j < 4; j++) { Bvs[bk][bc + j*16] = pv[j]; Bgs[bk][bc + j*16] = pg[j]; }
        __syncthreads();

        // prefetch next tile
        if (k0 + 16 < EDIM) {
            int kn = k0 + 16;
            if (aptr) {
                pa0 = *(const float4*)(aptr + kn + ac);
                pa1 = *(const float4*)(aptr + kn + ac + 4);
            } else { pa0 = make_float4(0,0,0,0); pa1 = pa0; }
            #pragma unroll
            for (int j = 0; j < 4; j++) {
                int n = n0 + bc + j * 16;
                size_t off = (size_t)(kn + bk) * HDIM + n;
                bool ok = (n < HDIM);
                pv[j] = ok ? wvp[off] : 0.f;
                pg[j] = ok ? wgp[off] : 0.f;
            }
        }

        #pragma unroll
        for (int kk = 0; kk < 16; kk++) {
            float a[8], bv4[4], bg4[4];
            #pragma unroll
            for (int i = 0; i < 8; i++) a[i] = As[kk][ty*8 + i];
            #pragma unroll
            for (int j = 0; j < 4; j++) { bv4[j] = Bvs[kk][tx*4 + j]; bg4[j] = Bgs[kk][tx*4 + j]; }
            #pragma unroll
            for (int i = 0; i < 8; i++)
                #pragma unroll
                for (int j = 0; j < 4; j++) {
                    accv[i][j] = fmaf(a[i], bv4[j], accv[i][j]);
                    accg[i][j] = fmaf(a[i], bg4[j], accg[i][j]);
                }
        }
        __syncthreads();
    }

    // epilogue: SwiGLU, write h (zero in pad columns [HDIM, HS) of last tile)
    #pragma unroll
    for (int i = 0; i < 8; i++) {
        int s = mt * 128 + ty * 8 + i;
        if (s >= cnt) continue;
        float* hrow = g_h + ((size_t)e * CAP + s) * HS;
        #pragma unroll
        for (int j = 0; j < 4; j++) {
            int n = n0 + tx * 4 + j;
            float val = 0.f;
            if (n < HDIM) {
                float hv = accv[i][j] + bv[(size_t)e * HDIM + n];
                float hg = accg[i][j] + bg[(size_t)e * HDIM + n];
                float sig = 1.f / (1.f + expf(-hv));
                val = hv * sig * hg;
            }
            if (n < HS) hrow[n] = val;
        }
    }
}

// ---------------- kernel 3: GEMM2  contrib[rank][tok] = w * (h Wo + bo) -----------
// tiles: BM=128, BN=128 (over E), BK=16; 256 threads; 8x8 microtile
#define KT2 2736   // 171 * 16 ; h pad columns are zero, Wo rows >= HDIM zero-filled
__global__ __launch_bounds__(256, 2)
void k_gemm2(const float* __restrict__ Wo, const float* __restrict__ bo) {
    const int e  = blockIdx.z;
    const int mt = blockIdx.y;
    const int nt = blockIdx.x;
    const int cnt = g_cnt[e];
    if (mt * 128 >= cnt) return;

    __shared__ float As[16][128];
    __shared__ float Bs[16][128];

    const int t  = threadIdx.x;
    const int ar = t >> 1;
    const int ac = (t & 1) * 8;
    const int aslot = mt * 128 + ar;
    const float* aptr = (aslot < cnt) ? (g_h + ((size_t)e * CAP + aslot) * HS) : nullptr;

    const int bk = t >> 4;         // 0..15
    const int bc = (t & 15) * 8;   // 0..120
    const int n0 = nt * 128;
    const float* wop = Wo + (size_t)e * HDIM * EDIM;

    const int tx = t & 15, ty = t >> 4;

    float acc[8][8];
    #pragma unroll
    for (int i = 0; i < 8; i++)
        #pragma unroll
        for (int j = 0; j < 8; j++) acc[i][j] = 0.f;

    float4 pa0, pa1, pb0, pb1;
    {
        if (aptr) {
            pa0 = *(const float4*)(aptr + ac);
            pa1 = *(const float4*)(aptr + ac + 4);
        } else { pa0 = make_float4(0,0,0,0); pa1 = pa0; }
        if (bk < HDIM) {
            const float* bp = wop + (size_t)bk * EDIM + n0 + bc;
            pb0 = *(const float4*)(bp);
            pb1 = *(const float4*)(bp + 4);
        } else { pb0 = make_float4(0,0,0,0); pb1 = pb0; }
    }

    for (int k0 = 0; k0 < KT2; k0 += 16) {
        As[ac+0][ar] = pa0.x; As[ac+1][ar] = pa0.y; As[ac+2][ar] = pa0.z; As[ac+3][ar] = pa0.w;
        As[ac+4][ar] = pa1.x; As[ac+5][ar] = pa1.y; As[ac+6][ar] = pa1.z; As[ac+7][ar] = pa1.w;
        *(float4*)&Bs[bk][bc]     = pb0;
        *(float4*)&Bs[bk][bc + 4] = pb1;
        __syncthreads();

        if (k0 + 16 < KT2) {
            int kn = k0 + 16;
            if (aptr) {
                pa0 = *(const float4*)(aptr + kn + ac);
                pa1 = *(const float4*)(aptr + kn + ac + 4);
            } else { pa0 = make_float4(0,0,0,0); pa1 = pa0; }
            if (kn + bk < HDIM) {
                const float* bp = wop + (size_t)(kn + bk) * EDIM + n0 + bc;
                pb0 = *(const float4*)(bp);
                pb1 = *(const float4*)(bp + 4);
            } else { pb0 = make_float4(0,0,0,0); pb1 = pb0; }
        }

        #pragma unroll
        for (int kk = 0; kk < 16; kk++) {
            float a[8], b[8];
            #pragma unroll
            for (int i = 0; i < 8; i++) a[i] = As[kk][ty*8 + i];
            #pragma unroll
            for (int j = 0; j < 8; j++) b[j] = Bs[kk][tx*8 + j];
            #pragma unroll
            for (int i = 0; i < 8; i++)
                #pragma unroll
                for (int j = 0; j < 8; j++)
                    acc[i][j] = fmaf(a[i], b[j], acc[i][j]);
        }
        __syncthreads();
    }

    // epilogue: scale by combine weight, plain store (unique per (token,rank))
    #pragma unroll
    for (int i = 0; i < 8; i++) {
        int s = mt * 128 + ty * 8 + i;
        if (s >= cnt) continue;
        int   info = g_slot[e][s];
        int   tok  = info >> 1;
        int   rank = info & 1;
        float w    = g_wt[e][s];
        float* dst = g_contrib[rank] + (size_t)tok * EDIM;
        #pragma unroll
        for (int j = 0; j < 8; j++) {
            int n = n0 + tx * 8 + j;
            dst[n] = w * (acc[i][j] + bo[(size_t)e * EDIM + n]);
        }
    }
}

// ---------------- kernel 4: residual + LayerNorm ----------------
__global__ void k_ln(const float* __restrict__ x,
                     const float* __restrict__ lng, const float* __restrict__ lnb,
                     float* __restrict__ out) {
    const int tok = blockIdx.x;
    const int t   = threadIdx.x;     // 256
    const float* xr = x + (size_t)tok * EDIM;
    const float* c0 = g_contrib[0] + (size_t)tok * EDIM;
    const float* c1 = g_contrib[1] + (size_t)tok * EDIM;

    float v[4];
    float s = 0.f;
    #pragma unroll
    for (int i = 0; i < 4; i++) {
        int idx = t + i * 256;
        v[i] = xr[idx] + c0[idx] + c1[idx];
        s += v[i];
    }
    __shared__ float red[256];
    red[t] = s; __syncthreads();
    #pragma unroll
    for (int off = 128; off > 0; off >>= 1) {
        if (t < off) red[t] += red[t + off];
        __syncthreads();
    }
    float mu = red[0] * (1.f / 1024.f);
    __syncthreads();

    float sq = 0.f;
    #pragma unroll
    for (int i = 0; i < 4; i++) { float d = v[i] - mu; sq += d * d; }
    red[t] = sq; __syncthreads();
    #pragma unroll
    for (int off = 128; off > 0; off >>= 1) {
        if (t < off) red[t] += red[t + off];
        __syncthreads();
    }
    float var  = red[0] * (1.f / 1024.f);
    float rstd = rsqrtf(var + 1e-5f);

    #pragma unroll
    for (int i = 0; i < 4; i++) {
        int idx = t + i * 256;
        out[(size_t)tok * EDIM + idx] = lng[idx] * (v[i] - mu) * rstd + lnb[idx];
    }
}

// ---------------- launcher ----------------
extern "C" void kernel_launch(void* const* d_in, const int* in_sizes, int n_in,
                              void* d_out, int out_size) {
    const float* x   = (const float*)d_in[0];
    const float* Wr  = (const float*)d_in[1];
    const float* Wv  = (const float*)d_in[2];
    const float* bv  = (const float*)d_in[3];
    const float* Wg  = (const float*)d_in[4];
    const float* bg  = (const float*)d_in[5];
    const float* Wo  = (const float*)d_in[6];
    const float* bo  = (const float*)d_in[7];
    const float* lng = (const float*)d_in[8];
    const float* lnb = (const float*)d_in[9];
    float* out = (float*)d_out;

    k_zero  <<<1, 32>>>();
    k_router<<<NTOK / 8, dim3(32, 8)>>>(x, Wr);
    k_gemm1 <<<dim3(43, 32, NEXP), 256>>>(x, Wv, bv, Wg, bg);
    k_gemm2 <<<dim3(8, 32, NEXP), 256>>>(Wo, bo);
    k_ln    <<<NTOK, 256>>>(x, lng, lnb, out);
}